// round 12
// baseline (speedup 1.0000x reference)
#include <cuda_runtime.h>
#include <math.h>

#define DEV_INLINE __device__ __forceinline__
typedef unsigned long long u64;

namespace {
constexpr int Bb   = 4;
constexpr int Hh   = 56;
constexpr int Wd   = 56;
constexpr int Ldim = Hh * Wd;          // 3136
constexpr int DM   = 96;
constexpr int DE   = 192;
constexpr int DS   = 16;
constexpr int DR   = 6;
constexpr int Kk   = 4;
constexpr int CX   = DR + 2 * DS;      // 38
constexpr int NC   = 49;               // chunks (divides 3136)
constexpr int LC   = Ldim / NC;        // 64 steps per chunk
}

// ---------------- scratch (static device allocations; no cudaMalloc) ----------
__device__ float  g_xx [Bb * DE * Ldim];             // (b,d,l) pre-conv
__device__ float  g_z  [Bb * DE * Ldim];             // (b,d,l) silu gate
__device__ float  g_xc [Bb * DE * Ldim];             // (b,d,l) post conv+silu
__device__ float  g_xcT[Bb * DE * Ldim];             // (b,d,l') transposed copy
__device__ float2 g_dus[Bb * Kk * Ldim * DE];        // (b,k,l,d) {dt, u}
__device__ float  g_Bsb[Bb * Kk * Ldim * DS];        // (b,k,l,n)
__device__ float  g_Csb[Bb * Kk * Ldim * DS];        // (b,k,l,n)
__device__ float  g_ys [Bb * Kk * Ldim * DE];        // (b,k,l,d)
__device__ float  g_gy [Bb * Ldim * DE];             // (b,l,d) gated+LN
__device__ float  g_q  [Bb * Kk * NC * DE * DS];     // per-chunk final h (from 0)
__device__ float  g_h0 [Bb * Kk * NC * DE * DS];     // per-chunk initial h
__device__ float  g_S  [Bb * Kk * NC * DE];          // per-chunk sum of dt

DEV_INLINE float siluf(float v) { return v / (1.f + __expf(-v)); }
DEV_INLINE float softplusf(float x) { return (x > 20.f) ? x : log1pf(__expf(x)); }
DEV_INLINE int   imapf(int l) { return (l % Wd) * Hh + l / Wd; }  // transpose map (involution, H==W)

// ---- packed f32x2 helpers (sm_100+; ptxas never auto-fuses these) ----
DEV_INLINE u64 pack2(float lo, float hi) {
    u64 r; asm("mov.b64 %0, {%1, %2};" : "=l"(r) : "f"(lo), "f"(hi)); return r;
}
DEV_INLINE void unpack2(u64 v, float& lo, float& hi) {
    asm("mov.b64 {%0, %1}, %2;" : "=f"(lo), "=f"(hi) : "l"(v));
}
DEV_INLINE u64 fma2(u64 a, u64 b, u64 c) {
    u64 d; asm("fma.rn.f32x2 %0, %1, %2, %3;" : "=l"(d) : "l"(a), "l"(b), "l"(c)); return d;
}
DEV_INLINE u64 mul2(u64 a, u64 b) {
    u64 d; asm("mul.rn.f32x2 %0, %1, %2;" : "=l"(d) : "l"(a), "l"(b)); return d;
}

// fast-structure check: An[n] == (n+1)*An0 (mamba A_log init)
DEV_INLINE bool fast_check(const float* alp, float An0) {
    bool fast = true;
#pragma unroll
    for (int n = 1; n < DS; n++) {
        float Ann = -__expf(__ldg(alp + n));
        fast = fast && (fabsf(Ann - (float)(n + 1) * An0) <= 1e-4f * fabsf(Ann));
    }
    return fast;
}

// =============================================================================
// Kernel A: in_proj GEMM (B*L,96)@(96,384)^T -> xx (b,d,l) and z=silu (b,d,l)
// float4 smem staging.
// =============================================================================
__global__ __launch_bounds__(256) void k_inproj(const float* __restrict__ x,
                                                const float* __restrict__ Wi) {
    __shared__ float xs[96][68];
    __shared__ float ws[96][68];
    const int t  = threadIdx.x;
    const int r0 = blockIdx.x * 64;   // over B*L
    const int c0 = blockIdx.y * 64;   // over 384

    for (int idx = t; idx < 64 * 24; idx += 256) {
        int r = idx / 24, kq = idx % 24;
        float4 xv = *(const float4*)&x [(size_t)(r0 + r) * 96 + 4 * kq];
        xs[4 * kq + 0][r] = xv.x;
        xs[4 * kq + 1][r] = xv.y;
        xs[4 * kq + 2][r] = xv.z;
        xs[4 * kq + 3][r] = xv.w;
        float4 wv = *(const float4*)&Wi[(size_t)(c0 + r) * 96 + 4 * kq];
        ws[4 * kq + 0][r] = wv.x;
        ws[4 * kq + 1][r] = wv.y;
        ws[4 * kq + 2][r] = wv.z;
        ws[4 * kq + 3][r] = wv.w;
    }
    __syncthreads();

    const int rl = (t & 15) * 4;
    const int cl = (t >> 4) * 4;
    u64 acc[2][4] = {};
#pragma unroll 4
    for (int k = 0; k < 96; k++) {
        ulonglong2 a2 = *(const ulonglong2*)&xs[k][rl];
        float4 bq = *(const float4*)&ws[k][cl];
        u64 b0 = pack2(bq.x, bq.x), b1 = pack2(bq.y, bq.y);
        u64 b2 = pack2(bq.z, bq.z), b3 = pack2(bq.w, bq.w);
        acc[0][0] = fma2(a2.x, b0, acc[0][0]);
        acc[0][1] = fma2(a2.x, b1, acc[0][1]);
        acc[0][2] = fma2(a2.x, b2, acc[0][2]);
        acc[0][3] = fma2(a2.x, b3, acc[0][3]);
        acc[1][0] = fma2(a2.y, b0, acc[1][0]);
        acc[1][1] = fma2(a2.y, b1, acc[1][1]);
        acc[1][2] = fma2(a2.y, b2, acc[1][2]);
        acc[1][3] = fma2(a2.y, b3, acc[1][3]);
    }

    const int bidx = r0 / Ldim;
    const int l0 = r0 - bidx * Ldim + rl;
#pragma unroll
    for (int ii = 0; ii < 4; ii++) {
        int ch = c0 + cl + ii;
        float4 v;
        unpack2(acc[0][ii], v.x, v.y);
        unpack2(acc[1][ii], v.z, v.w);
        if (ch < DE) {
            *(float4*)&g_xx[((size_t)bidx * DE + ch) * Ldim + l0] = v;
        } else {
            float4 s;
            s.x = siluf(v.x); s.y = siluf(v.y); s.z = siluf(v.z); s.w = siluf(v.w);
            *(float4*)&g_z[((size_t)bidx * DE + (ch - DE)) * Ldim + l0] = s;
        }
    }
}

// =============================================================================
// Kernel B: depthwise 3x3 conv + bias + SiLU; float4 I/O (W=56 divisible by 4).
// Emits g_xc and transposed g_xcT (via padded smem transpose).
// =============================================================================
__global__ __launch_bounds__(256) void k_conv(const float* __restrict__ cw,
                                              const float* __restrict__ cb) {
    __shared__ float img[Ldim];
    __shared__ float res[Hh * 57];
    const int t = threadIdx.x;
    const int d = blockIdx.x, b = blockIdx.y;
    const float4* src4 = (const float4*)(g_xx + ((size_t)b * DE + d) * Ldim);

    for (int i = t; i < Ldim / 4; i += 256)
        *(float4*)&img[4 * i] = __ldg(src4 + i);

    float w[9];
#pragma unroll
    for (int i = 0; i < 9; i++) w[i] = __ldg(&cw[d * 9 + i]);
    const float bias = __ldg(&cb[d]);
    __syncthreads();

    float4* xco4 = (float4*)(g_xc + ((size_t)b * DE + d) * Ldim);
    for (int i = t; i < Ldim / 4; i += 256) {
        int h   = i / 14;
        int w0c = (i % 14) * 4;
        float o[4];
#pragma unroll
        for (int q = 0; q < 4; q++) o[q] = bias;
#pragma unroll
        for (int r = 0; r < 3; r++) {
            int hh = h + r - 1;
            if (hh < 0 || hh >= Hh) continue;
            const float* row = &img[hh * Wd + w0c];
            float left  = (w0c > 0)      ? row[-1] : 0.f;
            float c0 = row[0], c1 = row[1], c2 = row[2], c3 = row[3];
            float right = (w0c + 4 < Wd) ? row[4]  : 0.f;
            float wl = w[r * 3 + 0], wm = w[r * 3 + 1], wr = w[r * 3 + 2];
            if (w0c > 0)      o[0] = fmaf(wl, left, o[0]);
            o[0] = fmaf(wm, c0, o[0]); o[0] = fmaf(wr, c1, o[0]);
            o[1] = fmaf(wl, c0, o[1]); o[1] = fmaf(wm, c1, o[1]); o[1] = fmaf(wr, c2, o[1]);
            o[2] = fmaf(wl, c1, o[2]); o[2] = fmaf(wm, c2, o[2]); o[2] = fmaf(wr, c3, o[2]);
            o[3] = fmaf(wl, c2, o[3]); o[3] = fmaf(wm, c3, o[3]);
            if (w0c + 4 < Wd) o[3] = fmaf(wr, right, o[3]);
        }
        float4 v;
        v.x = siluf(o[0]); v.y = siluf(o[1]); v.z = siluf(o[2]); v.w = siluf(o[3]);
        xco4[i] = v;
        res[h * 57 + w0c + 0] = v.x;
        res[h * 57 + w0c + 1] = v.y;
        res[h * 57 + w0c + 2] = v.z;
        res[h * 57 + w0c + 3] = v.w;
    }
    __syncthreads();

    float4* xto4 = (float4*)(g_xcT + ((size_t)b * DE + d) * Ldim);
    for (int i = t; i < Ldim / 4; i += 256) {
        int c0 = (4 * i) % Wd;
        int r0 = (4 * i) / Wd;
        float4 v;
        v.x = res[(c0 + 0) * 57 + r0];
        v.y = res[(c0 + 1) * 57 + r0];
        v.z = res[(c0 + 2) * 57 + r0];
        v.w = res[(c0 + 3) * 57 + r0];
        xto4[i] = v;
    }
}

// =============================================================================
// Kernel C: x_dbl proj + dt_proj + softplus; stores {dt, u} -> g_dus; Bs/Cs.
// (R8 configuration: 32-l tiles)
// =============================================================================
extern __shared__ float smemC[];
__global__ __launch_bounds__(256) void k_proj(const float* __restrict__ xpw_g,
                                              const float* __restrict__ dtw_g,
                                              const float* __restrict__ dtb_g) {
    float* xst  = smemC;                 // 192*34 = 6528
    float* xpw  = xst  + DE * 34;        // 7296 (reused as sdelta)
    float* dtw  = xpw  + CX * DE;        // 1152
    float* xdbl = dtw  + DE * DR;        // 38*33 = 1254
    float* sdelta = xpw;                 // reuse: 32*193 = 6176 <= 7296

    const int t  = threadIdx.x;
    const int l0 = blockIdx.x * 32;
    const int k  = blockIdx.y;
    const int b  = blockIdx.z;
    const size_t bk = (size_t)b * Kk + k;

    for (int idx = t; idx < CX * DE; idx += 256) xpw[idx] = xpw_g[(size_t)k * CX * DE + idx];
    for (int idx = t; idx < DE * DR; idx += 256) dtw[idx] = dtw_g[(size_t)k * DE * DR + idx];

    const float* usrc = (k & 1) ? g_xcT : g_xc;
    for (int idx = t; idx < DE * 32; idx += 256) {
        int dd = idx >> 5, j = idx & 31;
        int l = (k >= 2) ? (Ldim - 1 - (l0 + j)) : (l0 + j);
        xst[dd * 34 + j] = usrc[((size_t)b * DE + dd) * Ldim + l];
    }
    __syncthreads();

    // x_dbl: 19 c-pairs x 16 j-pairs, 2x2 micro-tile with packed j-pairs
    for (int u = t; u < 19 * 16; u += 256) {
        int j0 = 2 * (u & 15), c0 = 2 * (u >> 4);
        u64 acc0 = 0ull, acc1 = 0ull;
#pragma unroll 8
        for (int d = 0; d < DE; d++) {
            u64 x2 = *(const u64*)&xst[d * 34 + j0];
            float w0 = xpw[c0 * DE + d];
            float w1 = xpw[(c0 + 1) * DE + d];
            acc0 = fma2(x2, pack2(w0, w0), acc0);
            acc1 = fma2(x2, pack2(w1, w1), acc1);
        }
        float a00, a01, a10, a11;
        unpack2(acc0, a00, a01);
        unpack2(acc1, a10, a11);
        xdbl[c0 * 33 + j0]           = a00;
        xdbl[c0 * 33 + j0 + 1]       = a01;
        xdbl[(c0 + 1) * 33 + j0]     = a10;
        xdbl[(c0 + 1) * 33 + j0 + 1] = a11;
    }
    __syncthreads();   // xpw reads complete; region reusable as sdelta

    // Bs / Cs store
    for (int idx = t; idx < 32 * DS; idx += 256) {
        int j = idx >> 4, n = idx & 15;
        g_Bsb[(bk * Ldim + l0 + j) * DS + n] = xdbl[(DR + n) * 33 + j];
        g_Csb[(bk * Ldim + l0 + j) * DS + n] = xdbl[(DR + DS + n) * 33 + j];
    }

    // delta: softplus(dt_proj + bias)
    for (int u = t; u < 48 * 32; u += 256) {
        int j  = u & 31;
        int d0 = (u >> 5) * 4;
        float a0 = __ldg(&dtb_g[k * DE + d0 + 0]);
        float a1 = __ldg(&dtb_g[k * DE + d0 + 1]);
        float a2 = __ldg(&dtb_g[k * DE + d0 + 2]);
        float a3 = __ldg(&dtb_g[k * DE + d0 + 3]);
#pragma unroll
        for (int r = 0; r < DR; r++) {
            float xv = xdbl[r * 33 + j];
            a0 = fmaf(dtw[(d0 + 0) * DR + r], xv, a0);
            a1 = fmaf(dtw[(d0 + 1) * DR + r], xv, a1);
            a2 = fmaf(dtw[(d0 + 2) * DR + r], xv, a2);
            a3 = fmaf(dtw[(d0 + 3) * DR + r], xv, a3);
        }
        sdelta[j * 193 + d0 + 0] = softplusf(a0);
        sdelta[j * 193 + d0 + 1] = softplusf(a1);
        sdelta[j * 193 + d0 + 2] = softplusf(a2);
        sdelta[j * 193 + d0 + 3] = softplusf(a3);
    }
    __syncthreads();

    // fused {dt, u} writeout: coalesced 8B stores
    for (int idx = t; idx < 32 * DE; idx += 256) {
        int j = idx / DE, dd = idx % DE;
        float2 v;
        v.x = sdelta[j * 193 + dd];
        v.y = xst[dd * 34 + j];
        g_dus[(bk * Ldim + l0 + j) * DE + dd] = v;
    }
}

// =============================================================================
// Scan pass 1: thread owns 16 states (8 f32x2 pairs). B in SMEM; dus prefetched
// one 4-step group ahead (software pipeline over the L2 latency).
// =============================================================================
__global__ __launch_bounds__(192, 5) void k_scan1(const float* __restrict__ A_logs) {
    __shared__ float4 sB4[LC * 4];
    const int d = threadIdx.x;
    const int c = blockIdx.x, k = blockIdx.y, b = blockIdx.z;
    const size_t bk = (size_t)b * Kk + k;
    const int l0 = c * LC;

    const float4* bp4 = (const float4*)(g_Bsb + bk * Ldim * DS) + (size_t)l0 * 4;
    for (int i = d; i < LC * 4; i += 192) sB4[i] = bp4[i];

    const float* alp = A_logs + (size_t)(k * DE + d) * DS;
    const float An0 = -__expf(__ldg(alp));
    const bool fast = fast_check(alp, An0);

    const float2* dusp = g_dus + (bk * Ldim + l0) * DE + d;
    __syncthreads();

    if (fast) {
        u64 h2[8];
#pragma unroll
        for (int i = 0; i < 8; i++) h2[i] = 0ull;
        float S = 0.f;
        const ulonglong2* sB = (const ulonglong2*)sB4;

        float2 cu[4];
#pragma unroll
        for (int r = 0; r < 4; r++) cu[r] = __ldg(dusp + (size_t)r * DE);

        for (int j0 = 0; j0 < LC; j0 += 4) {
            float2 cun[4];
            if (j0 + 4 < LC) {
#pragma unroll
                for (int r = 0; r < 4; r++)
                    cun[r] = __ldg(dusp + (size_t)(j0 + 4 + r) * DE);
            }
#pragma unroll
            for (int r = 0; r < 4; r++) {
                float dt = cu[r].x, u = cu[r].y;
                float du = dt * u;
                S += dt;
                float e1 = __expf(dt * An0);
                float e2v = e1 * e1;
                u64 E0 = pack2(e1, e2v);
                u64 e22 = pack2(e2v, e2v);
                u64 E1 = mul2(E0, e22);
                u64 E2 = mul2(E1, e22);
                u64 E3 = mul2(E2, e22);
                float e7v, e8v; unpack2(E3, e7v, e8v);
                u64 e88 = pack2(e8v, e8v);
                u64 du2 = pack2(du, du);
                const ulonglong2* bl = sB + (size_t)(j0 + r) * 4;
                ulonglong2 B01 = bl[0];
                h2[0] = fma2(h2[0], E0, mul2(B01.x, du2));
                h2[1] = fma2(h2[1], E1, mul2(B01.y, du2));
                ulonglong2 B23 = bl[1];
                h2[2] = fma2(h2[2], E2, mul2(B23.x, du2));
                h2[3] = fma2(h2[3], E3, mul2(B23.y, du2));
                ulonglong2 B45 = bl[2];
                h2[4] = fma2(h2[4], mul2(E0, e88), mul2(B45.x, du2));
                h2[5] = fma2(h2[5], mul2(E1, e88), mul2(B45.y, du2));
                ulonglong2 B67 = bl[3];
                h2[6] = fma2(h2[6], mul2(E2, e88), mul2(B67.x, du2));
                h2[7] = fma2(h2[7], mul2(E3, e88), mul2(B67.y, du2));
            }
#pragma unroll
            for (int r = 0; r < 4; r++) cu[r] = cun[r];
        }
        float4* qo = (float4*)(g_q + ((bk * NC + c) * DE + d) * (size_t)DS);
#pragma unroll
        for (int q = 0; q < 4; q++) {
            float4 v;
            unpack2(h2[2 * q],     v.x, v.y);
            unpack2(h2[2 * q + 1], v.z, v.w);
            qo[q] = v;
        }
        g_S[(bk * NC + c) * DE + d] = S;
    } else {
        float h[DS];
#pragma unroll
        for (int n = 0; n < DS; n++) h[n] = 0.f;
        float An[DS];
#pragma unroll
        for (int n = 0; n < DS; n++) An[n] = -__expf(__ldg(alp + n));
        float S = 0.f;
        for (int j = 0; j < LC; j++) {
            float2 cu = __ldg(dusp + (size_t)j * DE);
            float dt = cu.x, u = cu.y;
            float du = dt * u;
            S += dt;
#pragma unroll
            for (int q = 0; q < 4; q++) {
                float4 Bq = sB4[j * 4 + q];
                h[4*q+0] = fmaf(h[4*q+0], __expf(dt * An[4*q+0]), du * Bq.x);
                h[4*q+1] = fmaf(h[4*q+1], __expf(dt * An[4*q+1]), du * Bq.y);
                h[4*q+2] = fmaf(h[4*q+2], __expf(dt * An[4*q+2]), du * Bq.z);
                h[4*q+3] = fmaf(h[4*q+3], __expf(dt * An[4*q+3]), du * Bq.w);
            }
        }
        float4* qo = (float4*)(g_q + ((bk * NC + c) * DE + d) * (size_t)DS);
#pragma unroll
        for (int q = 0; q < 4; q++)
            qo[q] = make_float4(h[4*q+0], h[4*q+1], h[4*q+2], h[4*q+3]);
        g_S[(bk * NC + c) * DE + d] = S;
    }
}

// =============================================================================
// Scan pass 2: serial combine across chunks. h0[c+1] = E_c h0[c] + q_c
// =============================================================================
__global__ __launch_bounds__(256) void k_scan2(const float* __restrict__ A_logs) {
    const int tid = blockIdx.x * 256 + threadIdx.x;   // < Bb*Kk*DE*DS
    const int n  = tid & 15;
    const int d  = (tid >> 4) % DE;
    const int bk = tid / (DE * DS);
    const int k  = bk & 3;
    const float An = -__expf(__ldg(&A_logs[(size_t)(k * DE + d) * DS + n]));
    float h = 0.f;
#pragma unroll 7
    for (int c = 0; c < NC; c++) {
        size_t base = (((size_t)bk * NC + c) * DE + d) * DS + n;
        g_h0[base] = h;
        float S  = __ldg(&g_S[((size_t)bk * NC + c) * DE + d]);
        float qv = __ldg(&g_q[base]);
        h = fmaf(h, __expf(An * S), qv);
    }
}

// =============================================================================
// Scan pass 3: rescan chunk from h0, emit y. B,C in SMEM; dus prefetched.
// =============================================================================
__global__ __launch_bounds__(192, 5) void k_scan3(const float* __restrict__ A_logs,
                                                  const float* __restrict__ Ds) {
    __shared__ float4 sB4[LC * 4];
    __shared__ float4 sC4[LC * 4];
    const int d = threadIdx.x;
    const int c = blockIdx.x, k = blockIdx.y, b = blockIdx.z;
    const size_t bk = (size_t)b * Kk + k;
    const int l0 = c * LC;

    const float4* bp4 = (const float4*)(g_Bsb + bk * Ldim * DS) + (size_t)l0 * 4;
    const float4* cp4 = (const float4*)(g_Csb + bk * Ldim * DS) + (size_t)l0 * 4;
    for (int i = d; i < LC * 4; i += 192) { sB4[i] = bp4[i]; sC4[i] = cp4[i]; }

    const float* alp = A_logs + (size_t)(k * DE + d) * DS;
    const float An0 = -__expf(__ldg(alp));
    const bool fast = fast_check(alp, An0);
    const float Dv = __ldg(&Ds[k * DE + d]);

    const float2* dusp = g_dus + (bk * Ldim + l0) * DE + d;
    float* yo = g_ys + (bk * Ldim + (size_t)l0) * DE + d;
    const float4* h0p = (const float4*)(g_h0 + ((bk * NC + c) * DE + d) * (size_t)DS);
    __syncthreads();

    if (fast) {
        u64 h2[8];
#pragma unroll
        for (int q = 0; q < 4; q++) {
            float4 v = __ldg(h0p + q);
            h2[2 * q]     = pack2(v.x, v.y);
            h2[2 * q + 1] = pack2(v.z, v.w);
        }
        const ulonglong2* sB = (const ulonglong2*)sB4;
        const ulonglong2* sC = (const ulonglong2*)sC4;

        float2 cu[4];
#pragma unroll
        for (int r = 0; r < 4; r++) cu[r] = __ldg(dusp + (size_t)r * DE);

        for (int j0 = 0; j0 < LC; j0 += 4) {
            float2 cun[4];
            if (j0 + 4 < LC) {
#pragma unroll
                for (int r = 0; r < 4; r++)
                    cun[r] = __ldg(dusp + (size_t)(j0 + 4 + r) * DE);
            }
#pragma unroll
            for (int r = 0; r < 4; r++) {
                int j = j0 + r;
                float dt = cu[r].x, u = cu[r].y;
                float du = dt * u;
                float e1 = __expf(dt * An0);
                float e2v = e1 * e1;
                u64 E0 = pack2(e1, e2v);
                u64 e22 = pack2(e2v, e2v);
                u64 E1 = mul2(E0, e22);
                u64 E2 = mul2(E1, e22);
                u64 E3 = mul2(E2, e22);
                float e7v, e8v; unpack2(E3, e7v, e8v);
                u64 e88 = pack2(e8v, e8v);
                u64 du2 = pack2(du, du);
                u64 y2 = pack2(Dv * u, 0.f);
                const ulonglong2* bl = sB + (size_t)j * 4;
                const ulonglong2* cl = sC + (size_t)j * 4;
                ulonglong2 B01 = bl[0], C01 = cl[0];
                h2[0] = fma2(h2[0], E0, mul2(B01.x, du2)); y2 = fma2(h2[0], C01.x, y2);
                h2[1] = fma2(h2[1], E1, mul2(B01.y, du2)); y2 = fma2(h2[1], C01.y, y2);
                ulonglong2 B23 = bl[1], C23 = cl[1];
                h2[2] = fma2(h2[2], E2, mul2(B23.x, du2)); y2 = fma2(h2[2], C23.x, y2);
                h2[3] = fma2(h2[3], E3, mul2(B23.y, du2)); y2 = fma2(h2[3], C23.y, y2);
                ulonglong2 B45 = bl[2], C45 = cl[2];
                h2[4] = fma2(h2[4], mul2(E0, e88), mul2(B45.x, du2)); y2 = fma2(h2[4], C45.x, y2);
                h2[5] = fma2(h2[5], mul2(E1, e88), mul2(B45.y, du2)); y2 = fma2(h2[5], C45.y, y2);
                ulonglong2 B67 = bl[3], C67 = cl[3];
                h2[6] = fma2(h2[6], mul2(E2, e88), mul2(B67.x, du2)); y2 = fma2(h2[6], C67.x, y2);
                h2[7] = fma2(h2[7], mul2(E3, e88), mul2(B67.y, du2)); y2 = fma2(h2[7], C67.y, y2);
                float ya, yb; unpack2(y2, ya, yb);
                yo[(size_t)j * DE] = ya + yb;
            }
#pragma unroll
            for (int r = 0; r < 4; r++) cu[r] = cun[r];
        }
    } else {
        float h[DS];
        float An[DS];
#pragma unroll
        for (int n = 0; n < DS; n++) An[n] = -__expf(__ldg(alp + n));
#pragma unroll
        for (int q = 0; q < 4; q++) {
            float4 v = __ldg(h0p + q);
            h[4*q+0] = v.x; h[4*q+1] = v.y; h[4*q+2] = v.z; h[4*q+3] = v.w;
        }
        for (int j = 0; j < LC; j++) {
            float2 cu = __ldg(dusp + (size_t)j * DE);
            float dt = cu.x, u = cu.y;
            float du = dt * u;
            float y = Dv * u;
#pragma unroll
            for (int q = 0; q < 4; q++) {
                float4 Bq = sB4[j * 4 + q];
                float4 Cq = sC4[j * 4 + q];
                h[4*q+0] = fmaf(h[4*q+0], __expf(dt * An[4*q+0]), du * Bq.x); y = fmaf(h[4*q+0], Cq.x, y);
                h[4*q+1] = fmaf(h[4*q+1], __expf(dt * An[4*q+1]), du * Bq.y); y = fmaf(h[4*q+1], Cq.y, y);
                h[4*q+2] = fmaf(h[4*q+2], __expf(dt * An[4*q+2]), du * Bq.z); y = fmaf(h[4*q+2], Cq.z, y);
                h[4*q+3] = fmaf(h[4*q+3], __expf(dt * An[4*q+3]), du * Bq.w); y = fmaf(h[4*q+3], Cq.w, y);
            }
            yo[(size_t)j * DE] = y;
        }
    }
}

// =============================================================================
// Kernel E1: cross-merge 4 directions + LayerNorm(192) + z gate -> g_gy (b,l,d)
// j-major vs tile (196-pad: 2-way max conflicts, 16B-aligned); float4 I/O.
// =============================================================================
__global__ __launch_bounds__(256) void k_merge_ln(const float* __restrict__ lnw,
                                                  const float* __restrict__ lnb) {
    __shared__ float vs[16][196];   // [j][d]
    __shared__ float smu[16], srs[16];
    const int t  = threadIdx.x;
    const int l0 = blockIdx.x * 16;
    const int b  = blockIdx.y;
    const size_t b4 = (size_t)b * Kk;

    // merge 4 directions, float4 over d
    for (int idx = t; idx < 16 * 48; idx += 256) {
        int j = idx / 48, q = idx % 48;
        int l  = l0 + j;
        int li = imapf(l);
        const float4 v0 = *(const float4*)&g_ys[((b4 + 0) * Ldim + l             ) * DE + 4 * q];
        const float4 v2 = *(const float4*)&g_ys[((b4 + 2) * Ldim + (Ldim - 1 - l)) * DE + 4 * q];
        const float4 v1 = *(const float4*)&g_ys[((b4 + 1) * Ldim + li            ) * DE + 4 * q];
        const float4 v3 = *(const float4*)&g_ys[((b4 + 3) * Ldim + (Ldim - 1 - li)) * DE + 4 * q];
        float4 s;
        s.x = v0.x + v1.x + v2.x + v3.x;
        s.y = v0.y + v1.y + v2.y + v3.y;
        s.z = v0.z + v1.z + v2.z + v3.z;
        s.w = v0.w + v1.w + v2.w + v3.w;
        *(float4*)&vs[j][4 * q] = s;
    }
    __syncthreads();

    // LN stats: 16 threads per j
    {
        int j = t >> 4, lane = t & 15;
        float s = 0.f, s2 = 0.f;
#pragma unroll
        for (int i = 0; i < DE / 16; i++) {
            float v = vs[j][lane + 16 * i];
            s += v;
            s2 = fmaf(v, v, s2);
        }
#pragma unroll
        for (int o = 8; o; o >>= 1) {
            s  += __shfl_xor_sync(0xffffffffu, s,  o, 16);
            s2 += __shfl_xor_sync(0xffffffffu, s2, o, 16);
        }
        if (lane == 0) {
            float mu  = s * (1.f / DE);
            float var = s2 * (1.f / DE) - mu * mu;
            smu[j] = mu;
            srs[j] = rsqrtf(var + 1e-5f);
        }
    }
    __syncthreads();

    // LN + z gate (j fast within warp -> z reads 64B-coalesced)
    for (int idx = t; idx < DE * 16; idx += 256) {
        int j  = idx & 15;
        int dd = idx >> 4;
        float v = vs[j][dd];
        float g = fmaf((v - smu[j]) * srs[j], __ldg(&lnw[dd]), __ldg(&lnb[dd]));
        vs[j][dd] = g * g_z[((size_t)b * DE + dd) * Ldim + l0 + j];
    }
    __syncthreads();

    // store g_gy (b,l,d), float4 over d
    for (int idx = t; idx < 16 * 48; idx += 256) {
        int j = idx / 48, q = idx % 48;
        *(float4*)&g_gy[((size_t)b * Ldim + l0 + j) * DE + 4 * q] =
            *(const float4*)&vs[j][4 * q];
    }
}

// =============================================================================
// Kernel E2: out_proj GEMM (B*L,192)@(192,96)^T -> out (b,l,96). f32x2 tile.
// float4 smem staging.
// =============================================================================
__global__ __launch_bounds__(256) void k_outproj(const float* __restrict__ Wo,
                                                 float* __restrict__ out) {
    __shared__ float as_s[64][68];
    __shared__ float ws_s[64][98];
    const int t  = threadIdx.x;
    const int r0 = blockIdx.x * 64;
    const int rl = (t & 15) * 4;
    const int c0 = (t >> 4) * 6;
    u64 acc[4][3] = {};

    for (int kc = 0; kc < DE; kc += 64) {
        __syncthreads();
        for (int idx = t; idx < 64 * 16; idx += 256) {
            int r = idx / 16, kq = idx % 16;
            float4 v = *(const float4*)&g_gy[(size_t)(r0 + r) * DE + kc + 4 * kq];
            as_s[4 * kq + 0][r] = v.x;
            as_s[4 * kq + 1][r] = v.y;
            as_s[4 * kq + 2][r] = v.z;
            as_s[4 * kq + 3][r] = v.w;
        }
        for (int idx = t; idx < 96 * 16; idx += 256) {
            int o = idx / 16, kq = idx % 16;
            float4 v = *(const float4*)&Wo[(size_t)o * DE + kc + 4 * kq];
            ws_s[4 * kq + 0][o] = v.x;
            ws_s[4 * kq + 1][o] = v.y;
            ws_s[4 * kq + 2][o] = v.z;
            ws_s[4 * kq + 3][o] = v.w;
        }
        __syncthreads();
#pragma unroll 4
        for (int kk = 0; kk < 64; kk++) {
            float4 aq = *(const float4*)&as_s[kk][rl];
            u64 a0 = pack2(aq.x, aq.x), a1 = pack2(aq.y, aq.y);
            u64 a2 = pack2(aq.z, aq.z), a3 = pack2(aq.w, aq.w);
            const u64* wp = (const u64*)&ws_s[kk][c0];
            u64 w0 = wp[0], w1 = wp[1], w2 = wp[2];
            acc[0][0] = fma2(a0, w0, acc[0][0]);
            acc[0][1] = fma2(a0, w1, acc[0][1]);
            acc[0][2] = fma2(a0, w2, acc[0][2]);
            acc[1][0] = fma2(a1, w0, acc[1][0]);
            acc[1][1] = fma2(a1, w1, acc[1][1]);
            acc[1][2] = fma2(a1, w2, acc[1][2]);
            acc[2][0] = fma2(a2, w0, acc[2][0]);
            acc[2][1] = fma2(a2, w1, acc[2][1]);
            acc[2][2] = fma2(a2, w2, acc[2][2]);
            acc[3][0] = fma2(a3, w0, acc[3][0]);
            acc[3][1] = fma2(a3, w1, acc[3][1]);
            acc[3][2] = fma2(a3, w2, acc[3][2]);
        }
    }

#pragma unroll
    for (int i = 0; i < 4; i++) {
        size_t row = (size_t)(r0 + rl + i);
#pragma unroll
        for (int j2 = 0; j2 < 3; j2++) {
            float2 v;
            unpack2(acc[i][j2], v.x, v.y);
            *(float2*)&out[row * DM + c0 + 2 * j2] = v;
        }
    }
}

// =============================================================================
extern "C" void kernel_launch(void* const* d_in, const int* in_sizes, int n_in,
                              void* d_out, int out_size) {
    const float* x    = (const float*)d_in[0];
    const float* ipw  = (const float*)d_in[1];
    const float* cw   = (const float*)d_in[2];
    const float* cb   = (const float*)d_in[3];
    const float* xpw  = (const float*)d_in[4];
    const float* dtw  = (const float*)d_in[5];
    const float* dtb  = (const float*)d_in[6];
    const float* alog = (const float*)d_in[7];
    const float* Dsp  = (const float*)d_in[8];
    const float* lnw  = (const float*)d_in[9];
    const float* lnb  = (const float*)d_in[10];
    const float* opw  = (const float*)d_in[11];
    float* out = (float*)d_out;

    const int smemC_bytes = (DE * 34 + CX * DE + DE * DR + CX * 33) * 4;
    cudaFuncSetAttribute(k_proj, cudaFuncAttributeMaxDynamicSharedMemorySize, smemC_bytes);

    dim3 gA(Bb * Ldim / 64, 384 / 64);
    k_inproj<<<gA, 256>>>(x, ipw);

    dim3 gB(DE, Bb);
    k_conv<<<gB, 256>>>(cw, cb);

    dim3 gC(Ldim / 32, Kk, Bb);
    k_proj<<<gC, 256, smemC_bytes>>>(xpw, dtw, dtb);

    dim3 gS(NC, Kk, Bb);
    k_scan1<<<gS, 192>>>(alog);
    k_scan2<<<(Bb * Kk * DE * DS) / 256, 256>>>(alog);
    k_scan3<<<gS, 192>>>(alog, Dsp);

    dim3 gE(Ldim / 16, Bb);
    k_merge_ln<<<gE, 256>>>(lnw, lnb);

    k_outproj<<<Bb * Ldim / 64, 256>>>(opw, out);
}

// round 13
// speedup vs baseline: 1.0331x; 1.0331x over previous
#include <cuda_runtime.h>
#include <math.h>

#define DEV_INLINE __device__ __forceinline__
typedef unsigned long long u64;

namespace {
constexpr int Bb   = 4;
constexpr int Hh   = 56;
constexpr int Wd   = 56;
constexpr int Ldim = Hh * Wd;          // 3136
constexpr int DM   = 96;
constexpr int DE   = 192;
constexpr int DS   = 16;
constexpr int DR   = 6;
constexpr int Kk   = 4;
constexpr int CX   = DR + 2 * DS;      // 38
constexpr int NC   = 49;               // chunks (divides 3136)
constexpr int LC   = Ldim / NC;        // 64 steps per chunk
}

// ---------------- scratch (static device allocations; no cudaMalloc) ----------
__device__ float  g_xx [Bb * DE * Ldim];             // (b,d,l) pre-conv
__device__ float  g_z  [Bb * DE * Ldim];             // (b,d,l) silu gate
__device__ float  g_xc [Bb * DE * Ldim];             // (b,d,l) post conv+silu
__device__ float  g_xcT[Bb * DE * Ldim];             // (b,d,l') transposed copy
__device__ float2 g_dus[Bb * Kk * Ldim * DE];        // (b,k,l,d) {dt, u}
__device__ float  g_Bsb[Bb * Kk * Ldim * DS];        // (b,k,l,n)
__device__ float  g_Csb[Bb * Kk * Ldim * DS];        // (b,k,l,n)
__device__ float  g_ys [Bb * Kk * Ldim * DE];        // (b,k,l,d)
__device__ float  g_q  [Bb * Kk * NC * DE * DS];     // per-chunk final h (from 0)
__device__ float  g_h0 [Bb * Kk * NC * DE * DS];     // per-chunk initial h
__device__ float  g_S  [Bb * Kk * NC * DE];          // per-chunk sum of dt

DEV_INLINE float siluf(float v) { return v / (1.f + __expf(-v)); }
DEV_INLINE float softplusf(float x) { return (x > 20.f) ? x : log1pf(__expf(x)); }
DEV_INLINE int   imapf(int l) { return (l % Wd) * Hh + l / Wd; }  // transpose map (involution, H==W)

// ---- packed f32x2 helpers (sm_100+; ptxas never auto-fuses these) ----
DEV_INLINE u64 pack2(float lo, float hi) {
    u64 r; asm("mov.b64 %0, {%1, %2};" : "=l"(r) : "f"(lo), "f"(hi)); return r;
}
DEV_INLINE void unpack2(u64 v, float& lo, float& hi) {
    asm("mov.b64 {%0, %1}, %2;" : "=f"(lo), "=f"(hi) : "l"(v));
}
DEV_INLINE u64 fma2(u64 a, u64 b, u64 c) {
    u64 d; asm("fma.rn.f32x2 %0, %1, %2, %3;" : "=l"(d) : "l"(a), "l"(b), "l"(c)); return d;
}
DEV_INLINE u64 mul2(u64 a, u64 b) {
    u64 d; asm("mul.rn.f32x2 %0, %1, %2;" : "=l"(d) : "l"(a), "l"(b)); return d;
}

// fast-structure check: An[n] == (n+1)*An0 (mamba A_log init)
DEV_INLINE bool fast_check(const float* alp, float An0) {
    bool fast = true;
#pragma unroll
    for (int n = 1; n < DS; n++) {
        float Ann = -__expf(__ldg(alp + n));
        fast = fast && (fabsf(Ann - (float)(n + 1) * An0) <= 1e-4f * fabsf(Ann));
    }
    return fast;
}

// =============================================================================
// Kernel A: in_proj GEMM (B*L,96)@(96,384)^T -> xx (b,d,l) and z=silu (b,d,l)
// (R11 staging)
// =============================================================================
__global__ __launch_bounds__(256) void k_inproj(const float* __restrict__ x,
                                                const float* __restrict__ Wi) {
    __shared__ float xs[96][68];
    __shared__ float ws[96][68];
    const int t  = threadIdx.x;
    const int r0 = blockIdx.x * 64;   // over B*L
    const int c0 = blockIdx.y * 64;   // over 384

    for (int idx = t; idx < 64 * 96; idx += 256) {
        int r = idx / 96, k = idx % 96;
        xs[k][r] = x [(size_t)(r0 + r) * 96 + k];
        ws[k][r] = Wi[(size_t)(c0 + r) * 96 + k];
    }
    __syncthreads();

    const int rl = (t & 15) * 4;
    const int cl = (t >> 4) * 4;
    u64 acc[2][4] = {};
#pragma unroll 4
    for (int k = 0; k < 96; k++) {
        ulonglong2 a2 = *(const ulonglong2*)&xs[k][rl];
        float4 bq = *(const float4*)&ws[k][cl];
        u64 b0 = pack2(bq.x, bq.x), b1 = pack2(bq.y, bq.y);
        u64 b2 = pack2(bq.z, bq.z), b3 = pack2(bq.w, bq.w);
        acc[0][0] = fma2(a2.x, b0, acc[0][0]);
        acc[0][1] = fma2(a2.x, b1, acc[0][1]);
        acc[0][2] = fma2(a2.x, b2, acc[0][2]);
        acc[0][3] = fma2(a2.x, b3, acc[0][3]);
        acc[1][0] = fma2(a2.y, b0, acc[1][0]);
        acc[1][1] = fma2(a2.y, b1, acc[1][1]);
        acc[1][2] = fma2(a2.y, b2, acc[1][2]);
        acc[1][3] = fma2(a2.y, b3, acc[1][3]);
    }

    const int bidx = r0 / Ldim;
    const int l0 = r0 - bidx * Ldim + rl;
#pragma unroll
    for (int ii = 0; ii < 4; ii++) {
        int ch = c0 + cl + ii;
        float4 v;
        unpack2(acc[0][ii], v.x, v.y);
        unpack2(acc[1][ii], v.z, v.w);
        if (ch < DE) {
            *(float4*)&g_xx[((size_t)bidx * DE + ch) * Ldim + l0] = v;
        } else {
            float4 s;
            s.x = siluf(v.x); s.y = siluf(v.y); s.z = siluf(v.z); s.w = siluf(v.w);
            *(float4*)&g_z[((size_t)bidx * DE + (ch - DE)) * Ldim + l0] = s;
        }
    }
}

// =============================================================================
// Kernel B: depthwise 3x3 conv + bias + SiLU; float4 I/O (W=56 divisible by 4).
// =============================================================================
__global__ __launch_bounds__(256) void k_conv(const float* __restrict__ cw,
                                              const float* __restrict__ cb) {
    __shared__ float img[Ldim];
    __shared__ float res[Hh * 57];
    const int t = threadIdx.x;
    const int d = blockIdx.x, b = blockIdx.y;
    const float4* src4 = (const float4*)(g_xx + ((size_t)b * DE + d) * Ldim);

    for (int i = t; i < Ldim / 4; i += 256)
        *(float4*)&img[4 * i] = __ldg(src4 + i);

    float w[9];
#pragma unroll
    for (int i = 0; i < 9; i++) w[i] = __ldg(&cw[d * 9 + i]);
    const float bias = __ldg(&cb[d]);
    __syncthreads();

    float4* xco4 = (float4*)(g_xc + ((size_t)b * DE + d) * Ldim);
    for (int i = t; i < Ldim / 4; i += 256) {
        int h   = i / 14;
        int w0c = (i % 14) * 4;
        float o[4];
#pragma unroll
        for (int q = 0; q < 4; q++) o[q] = bias;
#pragma unroll
        for (int r = 0; r < 3; r++) {
            int hh = h + r - 1;
            if (hh < 0 || hh >= Hh) continue;
            const float* row = &img[hh * Wd + w0c];
            float left  = (w0c > 0)      ? row[-1] : 0.f;
            float c0 = row[0], c1 = row[1], c2 = row[2], c3 = row[3];
            float right = (w0c + 4 < Wd) ? row[4]  : 0.f;
            float wl = w[r * 3 + 0], wm = w[r * 3 + 1], wr = w[r * 3 + 2];
            if (w0c > 0)      o[0] = fmaf(wl, left, o[0]);
            o[0] = fmaf(wm, c0, o[0]); o[0] = fmaf(wr, c1, o[0]);
            o[1] = fmaf(wl, c0, o[1]); o[1] = fmaf(wm, c1, o[1]); o[1] = fmaf(wr, c2, o[1]);
            o[2] = fmaf(wl, c1, o[2]); o[2] = fmaf(wm, c2, o[2]); o[2] = fmaf(wr, c3, o[2]);
            o[3] = fmaf(wl, c2, o[3]); o[3] = fmaf(wm, c3, o[3]);
            if (w0c + 4 < Wd) o[3] = fmaf(wr, right, o[3]);
        }
        float4 v;
        v.x = siluf(o[0]); v.y = siluf(o[1]); v.z = siluf(o[2]); v.w = siluf(o[3]);
        xco4[i] = v;
        res[h * 57 + w0c + 0] = v.x;
        res[h * 57 + w0c + 1] = v.y;
        res[h * 57 + w0c + 2] = v.z;
        res[h * 57 + w0c + 3] = v.w;
    }
    __syncthreads();

    float4* xto4 = (float4*)(g_xcT + ((size_t)b * DE + d) * Ldim);
    for (int i = t; i < Ldim / 4; i += 256) {
        int c0 = (4 * i) % Wd;
        int r0 = (4 * i) / Wd;
        float4 v;
        v.x = res[(c0 + 0) * 57 + r0];
        v.y = res[(c0 + 1) * 57 + r0];
        v.z = res[(c0 + 2) * 57 + r0];
        v.w = res[(c0 + 3) * 57 + r0];
        xto4[i] = v;
    }
}

// =============================================================================
// Kernel C: x_dbl proj + dt_proj + softplus; stores {dt, u} -> g_dus; Bs/Cs.
// =============================================================================
extern __shared__ float smemC[];
__global__ __launch_bounds__(256) void k_proj(const float* __restrict__ xpw_g,
                                              const float* __restrict__ dtw_g,
                                              const float* __restrict__ dtb_g) {
    float* xst  = smemC;                 // 192*34 = 6528
    float* xpw  = xst  + DE * 34;        // 7296 (reused as sdelta)
    float* dtw  = xpw  + CX * DE;        // 1152
    float* xdbl = dtw  + DE * DR;        // 38*33 = 1254
    float* sdelta = xpw;                 // reuse: 32*193 = 6176 <= 7296

    const int t  = threadIdx.x;
    const int l0 = blockIdx.x * 32;
    const int k  = blockIdx.y;
    const int b  = blockIdx.z;
    const size_t bk = (size_t)b * Kk + k;

    for (int idx = t; idx < CX * DE; idx += 256) xpw[idx] = xpw_g[(size_t)k * CX * DE + idx];
    for (int idx = t; idx < DE * DR; idx += 256) dtw[idx] = dtw_g[(size_t)k * DE * DR + idx];

    const float* usrc = (k & 1) ? g_xcT : g_xc;
    for (int idx = t; idx < DE * 32; idx += 256) {
        int dd = idx >> 5, j = idx & 31;
        int l = (k >= 2) ? (Ldim - 1 - (l0 + j)) : (l0 + j);
        xst[dd * 34 + j] = usrc[((size_t)b * DE + dd) * Ldim + l];
    }
    __syncthreads();

    // x_dbl: 19 c-pairs x 16 j-pairs, 2x2 micro-tile with packed j-pairs
    for (int u = t; u < 19 * 16; u += 256) {
        int j0 = 2 * (u & 15), c0 = 2 * (u >> 4);
        u64 acc0 = 0ull, acc1 = 0ull;
#pragma unroll 8
        for (int d = 0; d < DE; d++) {
            u64 x2 = *(const u64*)&xst[d * 34 + j0];
            float w0 = xpw[c0 * DE + d];
            float w1 = xpw[(c0 + 1) * DE + d];
            acc0 = fma2(x2, pack2(w0, w0), acc0);
            acc1 = fma2(x2, pack2(w1, w1), acc1);
        }
        float a00, a01, a10, a11;
        unpack2(acc0, a00, a01);
        unpack2(acc1, a10, a11);
        xdbl[c0 * 33 + j0]           = a00;
        xdbl[c0 * 33 + j0 + 1]       = a01;
        xdbl[(c0 + 1) * 33 + j0]     = a10;
        xdbl[(c0 + 1) * 33 + j0 + 1] = a11;
    }
    __syncthreads();   // xpw reads complete; region reusable as sdelta

    // Bs / Cs store
    for (int idx = t; idx < 32 * DS; idx += 256) {
        int j = idx >> 4, n = idx & 15;
        g_Bsb[(bk * Ldim + l0 + j) * DS + n] = xdbl[(DR + n) * 33 + j];
        g_Csb[(bk * Ldim + l0 + j) * DS + n] = xdbl[(DR + DS + n) * 33 + j];
    }

    // delta: softplus(dt_proj + bias)
    for (int u = t; u < 48 * 32; u += 256) {
        int j  = u & 31;
        int d0 = (u >> 5) * 4;
        float a0 = __ldg(&dtb_g[k * DE + d0 + 0]);
        float a1 = __ldg(&dtb_g[k * DE + d0 + 1]);
        float a2 = __ldg(&dtb_g[k * DE + d0 + 2]);
        float a3 = __ldg(&dtb_g[k * DE + d0 + 3]);
#pragma unroll
        for (int r = 0; r < DR; r++) {
            float xv = xdbl[r * 33 + j];
            a0 = fmaf(dtw[(d0 + 0) * DR + r], xv, a0);
            a1 = fmaf(dtw[(d0 + 1) * DR + r], xv, a1);
            a2 = fmaf(dtw[(d0 + 2) * DR + r], xv, a2);
            a3 = fmaf(dtw[(d0 + 3) * DR + r], xv, a3);
        }
        sdelta[j * 193 + d0 + 0] = softplusf(a0);
        sdelta[j * 193 + d0 + 1] = softplusf(a1);
        sdelta[j * 193 + d0 + 2] = softplusf(a2);
        sdelta[j * 193 + d0 + 3] = softplusf(a3);
    }
    __syncthreads();

    // fused {dt, u} writeout: coalesced 8B stores
    for (int idx = t; idx < 32 * DE; idx += 256) {
        int j = idx / DE, dd = idx % DE;
        float2 v;
        v.x = sdelta[j * 193 + dd];
        v.y = xst[dd * 34 + j];
        g_dus[(bk * Ldim + l0 + j) * DE + dd] = v;
    }
}

// =============================================================================
// Scan pass 1: thread owns 16 states (8 f32x2 pairs). B in SMEM; dus prefetched.
// =============================================================================
__global__ __launch_bounds__(192, 5) void k_scan1(const float* __restrict__ A_logs) {
    __shared__ float4 sB4[LC * 4];
    const int d = threadIdx.x;
    const int c = blockIdx.x, k = blockIdx.y, b = blockIdx.z;
    const size_t bk = (size_t)b * Kk + k;
    const int l0 = c * LC;

    const float4* bp4 = (const float4*)(g_Bsb + bk * Ldim * DS) + (size_t)l0 * 4;
    for (int i = d; i < LC * 4; i += 192) sB4[i] = bp4[i];

    const float* alp = A_logs + (size_t)(k * DE + d) * DS;
    const float An0 = -__expf(__ldg(alp));
    const bool fast = fast_check(alp, An0);

    const float2* dusp = g_dus + (bk * Ldim + l0) * DE + d;
    __syncthreads();

    if (fast) {
        u64 h2[8];
#pragma unroll
        for (int i = 0; i < 8; i++) h2[i] = 0ull;
        float S = 0.f;
        const ulonglong2* sB = (const ulonglong2*)sB4;

        float2 cu[4];
#pragma unroll
        for (int r = 0; r < 4; r++) cu[r] = __ldg(dusp + (size_t)r * DE);

        for (int j0 = 0; j0 < LC; j0 += 4) {
            float2 cun[4];
            if (j0 + 4 < LC) {
#pragma unroll
                for (int r = 0; r < 4; r++)
                    cun[r] = __ldg(dusp + (size_t)(j0 + 4 + r) * DE);
            }
#pragma unroll
            for (int r = 0; r < 4; r++) {
                float dt = cu[r].x, u = cu[r].y;
                float du = dt * u;
                S += dt;
                float e1 = __expf(dt * An0);
                float e2v = e1 * e1;
                u64 E0 = pack2(e1, e2v);
                u64 e22 = pack2(e2v, e2v);
                u64 E1 = mul2(E0, e22);
                u64 E2 = mul2(E1, e22);
                u64 E3 = mul2(E2, e22);
                float e7v, e8v; unpack2(E3, e7v, e8v);
                u64 e88 = pack2(e8v, e8v);
                u64 du2 = pack2(du, du);
                const ulonglong2* bl = sB + (size_t)(j0 + r) * 4;
                ulonglong2 B01 = bl[0];
                h2[0] = fma2(h2[0], E0, mul2(B01.x, du2));
                h2[1] = fma2(h2[1], E1, mul2(B01.y, du2));
                ulonglong2 B23 = bl[1];
                h2[2] = fma2(h2[2], E2, mul2(B23.x, du2));
                h2[3] = fma2(h2[3], E3, mul2(B23.y, du2));
                ulonglong2 B45 = bl[2];
                h2[4] = fma2(h2[4], mul2(E0, e88), mul2(B45.x, du2));
                h2[5] = fma2(h2[5], mul2(E1, e88), mul2(B45.y, du2));
                ulonglong2 B67 = bl[3];
                h2[6] = fma2(h2[6], mul2(E2, e88), mul2(B67.x, du2));
                h2[7] = fma2(h2[7], mul2(E3, e88), mul2(B67.y, du2));
            }
#pragma unroll
            for (int r = 0; r < 4; r++) cu[r] = cun[r];
        }
        float4* qo = (float4*)(g_q + ((bk * NC + c) * DE + d) * (size_t)DS);
#pragma unroll
        for (int q = 0; q < 4; q++) {
            float4 v;
            unpack2(h2[2 * q],     v.x, v.y);
            unpack2(h2[2 * q + 1], v.z, v.w);
            qo[q] = v;
        }
        g_S[(bk * NC + c) * DE + d] = S;
    } else {
        float h[DS];
#pragma unroll
        for (int n = 0; n < DS; n++) h[n] = 0.f;
        float An[DS];
#pragma unroll
        for (int n = 0; n < DS; n++) An[n] = -__expf(__ldg(alp + n));
        float S = 0.f;
        for (int j = 0; j < LC; j++) {
            float2 cu = __ldg(dusp + (size_t)j * DE);
            float dt = cu.x, u = cu.y;
            float du = dt * u;
            S += dt;
#pragma unroll
            for (int q = 0; q < 4; q++) {
                float4 Bq = sB4[j * 4 + q];
                h[4*q+0] = fmaf(h[4*q+0], __expf(dt * An[4*q+0]), du * Bq.x);
                h[4*q+1] = fmaf(h[4*q+1], __expf(dt * An[4*q+1]), du * Bq.y);
                h[4*q+2] = fmaf(h[4*q+2], __expf(dt * An[4*q+2]), du * Bq.z);
                h[4*q+3] = fmaf(h[4*q+3], __expf(dt * An[4*q+3]), du * Bq.w);
            }
        }
        float4* qo = (float4*)(g_q + ((bk * NC + c) * DE + d) * (size_t)DS);
#pragma unroll
        for (int q = 0; q < 4; q++)
            qo[q] = make_float4(h[4*q+0], h[4*q+1], h[4*q+2], h[4*q+3]);
        g_S[(bk * NC + c) * DE + d] = S;
    }
}

// =============================================================================
// Scan pass 2: serial combine across chunks. h0[c+1] = E_c h0[c] + q_c
// =============================================================================
__global__ __launch_bounds__(256) void k_scan2(const float* __restrict__ A_logs) {
    const int tid = blockIdx.x * 256 + threadIdx.x;   // < Bb*Kk*DE*DS
    const int n  = tid & 15;
    const int d  = (tid >> 4) % DE;
    const int bk = tid / (DE * DS);
    const int k  = bk & 3;
    const float An = -__expf(__ldg(&A_logs[(size_t)(k * DE + d) * DS + n]));
    float h = 0.f;
#pragma unroll 7
    for (int c = 0; c < NC; c++) {
        size_t base = (((size_t)bk * NC + c) * DE + d) * DS + n;
        g_h0[base] = h;
        float S  = __ldg(&g_S[((size_t)bk * NC + c) * DE + d]);
        float qv = __ldg(&g_q[base]);
        h = fmaf(h, __expf(An * S), qv);
    }
}

// =============================================================================
// Scan pass 3: rescan chunk from h0, emit y. B,C in SMEM; dus prefetched.
// =============================================================================
__global__ __launch_bounds__(192, 5) void k_scan3(const float* __restrict__ A_logs,
                                                  const float* __restrict__ Ds) {
    __shared__ float4 sB4[LC * 4];
    __shared__ float4 sC4[LC * 4];
    const int d = threadIdx.x;
    const int c = blockIdx.x, k = blockIdx.y, b = blockIdx.z;
    const size_t bk = (size_t)b * Kk + k;
    const int l0 = c * LC;

    const float4* bp4 = (const float4*)(g_Bsb + bk * Ldim * DS) + (size_t)l0 * 4;
    const float4* cp4 = (const float4*)(g_Csb + bk * Ldim * DS) + (size_t)l0 * 4;
    for (int i = d; i < LC * 4; i += 192) { sB4[i] = bp4[i]; sC4[i] = cp4[i]; }

    const float* alp = A_logs + (size_t)(k * DE + d) * DS;
    const float An0 = -__expf(__ldg(alp));
    const bool fast = fast_check(alp, An0);
    const float Dv = __ldg(&Ds[k * DE + d]);

    const float2* dusp = g_dus + (bk * Ldim + l0) * DE + d;
    float* yo = g_ys + (bk * Ldim + (size_t)l0) * DE + d;
    const float4* h0p = (const float4*)(g_h0 + ((bk * NC + c) * DE + d) * (size_t)DS);
    __syncthreads();

    if (fast) {
        u64 h2[8];
#pragma unroll
        for (int q = 0; q < 4; q++) {
            float4 v = __ldg(h0p + q);
            h2[2 * q]     = pack2(v.x, v.y);
            h2[2 * q + 1] = pack2(v.z, v.w);
        }
        const ulonglong2* sB = (const ulonglong2*)sB4;
        const ulonglong2* sC = (const ulonglong2*)sC4;

        float2 cu[4];
#pragma unroll
        for (int r = 0; r < 4; r++) cu[r] = __ldg(dusp + (size_t)r * DE);

        for (int j0 = 0; j0 < LC; j0 += 4) {
            float2 cun[4];
            if (j0 + 4 < LC) {
#pragma unroll
                for (int r = 0; r < 4; r++)
                    cun[r] = __ldg(dusp + (size_t)(j0 + 4 + r) * DE);
            }
#pragma unroll
            for (int r = 0; r < 4; r++) {
                int j = j0 + r;
                float dt = cu[r].x, u = cu[r].y;
                float du = dt * u;
                float e1 = __expf(dt * An0);
                float e2v = e1 * e1;
                u64 E0 = pack2(e1, e2v);
                u64 e22 = pack2(e2v, e2v);
                u64 E1 = mul2(E0, e22);
                u64 E2 = mul2(E1, e22);
                u64 E3 = mul2(E2, e22);
                float e7v, e8v; unpack2(E3, e7v, e8v);
                u64 e88 = pack2(e8v, e8v);
                u64 du2 = pack2(du, du);
                u64 y2 = pack2(Dv * u, 0.f);
                const ulonglong2* bl = sB + (size_t)j * 4;
                const ulonglong2* cl = sC + (size_t)j * 4;
                ulonglong2 B01 = bl[0], C01 = cl[0];
                h2[0] = fma2(h2[0], E0, mul2(B01.x, du2)); y2 = fma2(h2[0], C01.x, y2);
                h2[1] = fma2(h2[1], E1, mul2(B01.y, du2)); y2 = fma2(h2[1], C01.y, y2);
                ulonglong2 B23 = bl[1], C23 = cl[1];
                h2[2] = fma2(h2[2], E2, mul2(B23.x, du2)); y2 = fma2(h2[2], C23.x, y2);
                h2[3] = fma2(h2[3], E3, mul2(B23.y, du2)); y2 = fma2(h2[3], C23.y, y2);
                ulonglong2 B45 = bl[2], C45 = cl[2];
                h2[4] = fma2(h2[4], mul2(E0, e88), mul2(B45.x, du2)); y2 = fma2(h2[4], C45.x, y2);
                h2[5] = fma2(h2[5], mul2(E1, e88), mul2(B45.y, du2)); y2 = fma2(h2[5], C45.y, y2);
                ulonglong2 B67 = bl[3], C67 = cl[3];
                h2[6] = fma2(h2[6], mul2(E2, e88), mul2(B67.x, du2)); y2 = fma2(h2[6], C67.x, y2);
                h2[7] = fma2(h2[7], mul2(E3, e88), mul2(B67.y, du2)); y2 = fma2(h2[7], C67.y, y2);
                float ya, yb; unpack2(y2, ya, yb);
                yo[(size_t)j * DE] = ya + yb;
            }
#pragma unroll
            for (int r = 0; r < 4; r++) cu[r] = cun[r];
        }
    } else {
        float h[DS];
        float An[DS];
#pragma unroll
        for (int n = 0; n < DS; n++) An[n] = -__expf(__ldg(alp + n));
#pragma unroll
        for (int q = 0; q < 4; q++) {
            float4 v = __ldg(h0p + q);
            h[4*q+0] = v.x; h[4*q+1] = v.y; h[4*q+2] = v.z; h[4*q+3] = v.w;
        }
        for (int j = 0; j < LC; j++) {
            float2 cu = __ldg(dusp + (size_t)j * DE);
            float dt = cu.x, u = cu.y;
            float du = dt * u;
            float y = Dv * u;
#pragma unroll
            for (int q = 0; q < 4; q++) {
                float4 Bq = sB4[j * 4 + q];
                float4 Cq = sC4[j * 4 + q];
                h[4*q+0] = fmaf(h[4*q+0], __expf(dt * An[4*q+0]), du * Bq.x); y = fmaf(h[4*q+0], Cq.x, y);
                h[4*q+1] = fmaf(h[4*q+1], __expf(dt * An[4*q+1]), du * Bq.y); y = fmaf(h[4*q+1], Cq.y, y);
                h[4*q+2] = fmaf(h[4*q+2], __expf(dt * An[4*q+2]), du * Bq.z); y = fmaf(h[4*q+2], Cq.z, y);
                h[4*q+3] = fmaf(h[4*q+3], __expf(dt * An[4*q+3]), du * Bq.w); y = fmaf(h[4*q+3], Cq.w, y);
            }
            yo[(size_t)j * DE] = y;
        }
    }
}

// =============================================================================
// Kernel E (fused): cross-merge + LayerNorm + z gate + out_proj GEMM -> out.
// Block = 64 l-positions of one b. vs[d][j] tile, then R11-style GEMM from SMEM.
// Dynamic SMEM: vs[192*68] | ws[64*98] | smu[64] | srs[64]  (~78KB, 2 blocks/SM)
// =============================================================================
__global__ __launch_bounds__(256) void k_mergeproj(const float* __restrict__ lnw,
                                                   const float* __restrict__ lnb,
                                                   const float* __restrict__ Wo,
                                                   float* __restrict__ out) {
    float* vs  = smemC;               // [DE][68]
    float* ws  = vs + DE * 68;        // [64][98]
    float* smu = ws + 64 * 98;        // [64]
    float* srs = smu + 64;            // [64]

    const int t  = threadIdx.x;
    const int r0 = blockIdx.x * 64;   // over B*L (64 | 3136 so never crosses b)
    const int b  = r0 / Ldim;
    const int l0 = r0 - b * Ldim;
    const size_t b4 = (size_t)b * Kk;

    // ---- merge 4 directions: 64 j x 48 float4-quads over d ----
    for (int idx = t; idx < 64 * 48; idx += 256) {
        int j = idx / 48, q = idx % 48;
        int l  = l0 + j;
        int li = imapf(l);
        const float4 v0 = *(const float4*)&g_ys[((b4 + 0) * Ldim + l             ) * DE + 4 * q];
        const float4 v2 = *(const float4*)&g_ys[((b4 + 2) * Ldim + (Ldim - 1 - l)) * DE + 4 * q];
        const float4 v1 = *(const float4*)&g_ys[((b4 + 1) * Ldim + li            ) * DE + 4 * q];
        const float4 v3 = *(const float4*)&g_ys[((b4 + 3) * Ldim + (Ldim - 1 - li)) * DE + 4 * q];
        vs[(4 * q + 0) * 68 + j] = v0.x + v1.x + v2.x + v3.x;
        vs[(4 * q + 1) * 68 + j] = v0.y + v1.y + v2.y + v3.y;
        vs[(4 * q + 2) * 68 + j] = v0.z + v1.z + v2.z + v3.z;
        vs[(4 * q + 3) * 68 + j] = v0.w + v1.w + v2.w + v3.w;
    }
    __syncthreads();

    // ---- LN stats: 4 threads per j (64 j x 4 lanes = 256) ----
    {
        int j = t >> 2, lane = t & 3;
        float s = 0.f, s2 = 0.f;
#pragma unroll
        for (int i = 0; i < DE / 4; i++) {
            float v = vs[(lane + 4 * i) * 68 + j];
            s += v;
            s2 = fmaf(v, v, s2);
        }
#pragma unroll
        for (int o = 2; o; o >>= 1) {
            s  += __shfl_xor_sync(0xffffffffu, s,  o, 4);
            s2 += __shfl_xor_sync(0xffffffffu, s2, o, 4);
        }
        if (lane == 0) {
            float mu  = s * (1.f / DE);
            float var = s2 * (1.f / DE) - mu * mu;
            smu[j] = mu;
            srs[j] = rsqrtf(var + 1e-5f);
        }
    }
    __syncthreads();

    // ---- LN + z gate (j fast -> coalesced z reads) ----
    for (int idx = t; idx < DE * 64; idx += 256) {
        int dd = idx / 64, j = idx % 64;
        float v = vs[dd * 68 + j];
        float g = fmaf((v - smu[j]) * srs[j], __ldg(&lnw[dd]), __ldg(&lnb[dd]));
        vs[dd * 68 + j] = g * g_z[((size_t)b * DE + dd) * Ldim + l0 + j];
    }
    __syncthreads();

    // ---- out_proj GEMM (A = vs in SMEM, Wo staged per 64-k chunk) ----
    const int rl = (t & 15) * 4;
    const int c0 = (t >> 4) * 6;
    u64 acc[4][3] = {};

    for (int kc = 0; kc < DE; kc += 64) {
        if (kc) __syncthreads();
        for (int idx = t; idx < 96 * 64; idx += 256) {
            int o = idx >> 6, kk = idx & 63;
            ws[kk * 98 + o] = Wo[(size_t)o * DE + kc + kk];
        }
        __syncthreads();
#pragma unroll 4
        for (int kk = 0; kk < 64; kk++) {
            float4 aq = *(const float4*)&vs[(kc + kk) * 68 + rl];
            u64 a0 = pack2(aq.x, aq.x), a1 = pack2(aq.y, aq.y);
            u64 a2 = pack2(aq.z, aq.z), a3 = pack2(aq.w, aq.w);
            const u64* wp = (const u64*)&ws[kk * 98 + c0];
            u64 w0 = wp[0], w1 = wp[1], w2 = wp[2];
            acc[0][0] = fma2(a0, w0, acc[0][0]);
            acc[0][1] = fma2(a0, w1, acc[0][1]);
            acc[0][2] = fma2(a0, w2, acc[0][2]);
            acc[1][0] = fma2(a1, w0, acc[1][0]);
            acc[1][1] = fma2(a1, w1, acc[1][1]);
            acc[1][2] = fma2(a1, w2, acc[1][2]);
            acc[2][0] = fma2(a2, w0, acc[2][0]);
            acc[2][1] = fma2(a2, w1, acc[2][1]);
            acc[2][2] = fma2(a2, w2, acc[2][2]);
            acc[3][0] = fma2(a3, w0, acc[3][0]);
            acc[3][1] = fma2(a3, w1, acc[3][1]);
            acc[3][2] = fma2(a3, w2, acc[3][2]);
        }
    }

#pragma unroll
    for (int i = 0; i < 4; i++) {
        size_t row = (size_t)(r0 + rl + i);
#pragma unroll
        for (int j2 = 0; j2 < 3; j2++) {
            float2 v;
            unpack2(acc[i][j2], v.x, v.y);
            *(float2*)&out[row * DM + c0 + 2 * j2] = v;
        }
    }
}

// =============================================================================
extern "C" void kernel_launch(void* const* d_in, const int* in_sizes, int n_in,
                              void* d_out, int out_size) {
    const float* x    = (const float*)d_in[0];
    const float* ipw  = (const float*)d_in[1];
    const float* cw   = (const float*)d_in[2];
    const float* cb   = (const float*)d_in[3];
    const float* xpw  = (const float*)d_in[4];
    const float* dtw  = (const float*)d_in[5];
    const float* dtb  = (const float*)d_in[6];
    const float* alog = (const float*)d_in[7];
    const float* Dsp  = (const float*)d_in[8];
    const float* lnw  = (const float*)d_in[9];
    const float* lnb  = (const float*)d_in[10];
    const float* opw  = (const float*)d_in[11];
    float* out = (float*)d_out;

    const int smemC_bytes = (DE * 34 + CX * DE + DE * DR + CX * 33) * 4;
    cudaFuncSetAttribute(k_proj, cudaFuncAttributeMaxDynamicSharedMemorySize, smemC_bytes);
    const int smemE_bytes = (DE * 68 + 64 * 98 + 128) * 4;
    cudaFuncSetAttribute(k_mergeproj, cudaFuncAttributeMaxDynamicSharedMemorySize, smemE_bytes);

    dim3 gA(Bb * Ldim / 64, 384 / 64);
    k_inproj<<<gA, 256>>>(x, ipw);

    dim3 gB(DE, Bb);
    k_conv<<<gB, 256>>>(cw, cb);

    dim3 gC(Ldim / 32, Kk, Bb);
    k_proj<<<gC, 256, smemC_bytes>>>(xpw, dtw, dtb);

    dim3 gS(NC, Kk, Bb);
    k_scan1<<<gS, 192>>>(alog);
    k_scan2<<<(Bb * Kk * DE * DS) / 256, 256>>>(alog);
    k_scan3<<<gS, 192>>>(alog, Dsp);

    k_mergeproj<<<Bb * Ldim / 64, 256, smemE_bytes>>>(lnw, lnb, opw, out);
}